// round 2
// baseline (speedup 1.0000x reference)
#include <cuda_runtime.h>
#include <cstdint>
#include <cstddef>

#define S 2048
#define D 512
#define NB 4           // batch
#define BM 128
#define BN 128
#define BK 16
#define EPSI 0.01f

// ----------------- device scratch (no allocations allowed) -----------------
__device__ __align__(128) float g_M [(size_t)NB * S * D];        // 16 MB
__device__ __align__(128) float g_W [(size_t)NB * S * S];        // 64 MB
__device__ __align__(128) float g_Vt[(size_t)NB * D * S];        // 16 MB
__device__ __align__(128) float g_rp[(size_t)NB * (S / BN) * S]; // partial row sums
__device__ __align__(128) float g_ri[NB * S];                    // 1 / l1
__device__ __align__(128) float g_m2[NB * S];                    // ||M_i||^2
__device__ __align__(128) float g_v2[NB * S];                    // ||V_j||^2

// ----------------- row squared-norm: one warp per row -----------------
__global__ void rownorm_kernel(const float* __restrict__ X, float* __restrict__ out,
                               int cols, int nrows) {
    int warp = (blockIdx.x * blockDim.x + threadIdx.x) >> 5;
    int lane = threadIdx.x & 31;
    if (warp >= nrows) return;
    const float* row = X + (size_t)warp * cols;
    float s = 0.f;
    for (int c = lane * 4; c < cols; c += 128) {
        float4 v = *(const float4*)(row + c);
        s += v.x * v.x + v.y * v.y + v.z * v.z + v.w * v.w;
    }
    #pragma unroll
    for (int off = 16; off >= 1; off >>= 1)
        s += __shfl_xor_sync(0xffffffffu, s, off);
    if (lane == 0) out[warp] = s;
}

// ----------------- V transpose: [b][j][d] -> [b][d][j] -----------------
__global__ void transpose_kernel(const float* __restrict__ V, float* __restrict__ Vt) {
    __shared__ float tile[32][33];
    int b  = blockIdx.z;
    int d0 = blockIdx.x * 32;
    int j0 = blockIdx.y * 32;
    int tx = threadIdx.x, ty = threadIdx.y;  // 32 x 8
    #pragma unroll
    for (int r = 0; r < 32; r += 8)
        tile[ty + r][tx] = V[((size_t)b * S + j0 + ty + r) * D + d0 + tx];
    __syncthreads();
    #pragma unroll
    for (int r = 0; r < 32; r += 8)
        Vt[((size_t)b * D + d0 + ty + r) * S + j0 + tx] = tile[tx][ty + r];
}

// ----------------- final l1 reduce + reciprocal -----------------
__global__ void reduce_rinv_kernel() {
    int idx = blockIdx.x * blockDim.x + threadIdx.x;   // b*S + i
    if (idx >= NB * S) return;
    int b = idx / S, i = idx - b * S;
    float s = 0.f;
    #pragma unroll
    for (int t = 0; t < S / BN; ++t)
        s += g_rp[((size_t)(b * (S / BN) + t)) * S + i];
    g_ri[idx] = 1.0f / fmaxf(s, 1e-12f);
}

// ----------------- fused SGEMM core -----------------
// C[b][i][n] = sum_k Aop[b][i][k] * Bop[b][k][n]
// MODE 0: plain store to Cout
// MODE 1: dist/weight epilogue -> g_W + per-tile row sums -> g_rp
// MODE 2: scale rows by g_ri, store to Cout
template <int NDIM, int KDIM, int MODE>
__global__ void __launch_bounds__(256, 2)
gemm_kernel(const float* __restrict__ Aop, const float* __restrict__ Bop,
            float* __restrict__ Cout, const float* __restrict__ Wsrc) {
    __shared__ float sA[2][BK][BM];
    __shared__ float sB[2][BK][BN];
    __shared__ float sRed[BM][17];

    const int b     = blockIdx.z;
    const int mBase = blockIdx.y * BM;
    const int nBase = blockIdx.x * BN;

    const float* Ab = Aop + (size_t)b * S * KDIM + (size_t)mBase * KDIM;
    const float* Bb = Bop + (size_t)b * KDIM * NDIM;

    const int tid = threadIdx.x;
    const int tx = tid & 15, ty = tid >> 4;

    // global-load assignments
    const int rA = tid >> 2;            // 0..63   (and +64)
    const int kA = (tid & 3) * 4;       // 0,4,8,12
    const int kB = tid >> 5;            // 0..7    (and +8)
    const int cB = (tid & 31) * 4;      // 0..124

    float acc[8][8];
    #pragma unroll
    for (int i = 0; i < 8; ++i)
        #pragma unroll
        for (int j = 0; j < 8; ++j) acc[i][j] = 0.f;

    // prologue: tile 0
    float4 a0 = *(const float4*)(Ab + (size_t)rA * KDIM + kA);
    float4 a1 = *(const float4*)(Ab + (size_t)(rA + 64) * KDIM + kA);
    float4 b0 = *(const float4*)(Bb + (size_t)kB * NDIM + nBase + cB);
    float4 b1 = *(const float4*)(Bb + (size_t)(kB + 8) * NDIM + nBase + cB);
    sA[0][kA + 0][rA] = a0.x; sA[0][kA + 1][rA] = a0.y;
    sA[0][kA + 2][rA] = a0.z; sA[0][kA + 3][rA] = a0.w;
    sA[0][kA + 0][rA + 64] = a1.x; sA[0][kA + 1][rA + 64] = a1.y;
    sA[0][kA + 2][rA + 64] = a1.z; sA[0][kA + 3][rA + 64] = a1.w;
    *(float4*)&sB[0][kB][cB]     = b0;
    *(float4*)&sB[0][kB + 8][cB] = b1;
    __syncthreads();

    const int nT = KDIM / BK;
    int buf = 0;
    for (int t = 0; t < nT; ++t) {
        float4 na0, na1, nb0, nb1;
        const bool more = (t + 1 < nT);
        if (more) {
            const float* An = Ab + (t + 1) * BK;
            na0 = *(const float4*)(An + (size_t)rA * KDIM + kA);
            na1 = *(const float4*)(An + (size_t)(rA + 64) * KDIM + kA);
            const float* Bn = Bb + (size_t)(t + 1) * BK * NDIM + nBase;
            nb0 = *(const float4*)(Bn + (size_t)kB * NDIM + cB);
            nb1 = *(const float4*)(Bn + (size_t)(kB + 8) * NDIM + cB);
        }
        #pragma unroll
        for (int k = 0; k < BK; ++k) {
            float ar[8], br[8];
            *(float4*)&ar[0] = *(const float4*)&sA[buf][k][ty * 4];
            *(float4*)&ar[4] = *(const float4*)&sA[buf][k][64 + ty * 4];
            *(float4*)&br[0] = *(const float4*)&sB[buf][k][tx * 4];
            *(float4*)&br[4] = *(const float4*)&sB[buf][k][64 + tx * 4];
            #pragma unroll
            for (int i = 0; i < 8; ++i)
                #pragma unroll
                for (int j = 0; j < 8; ++j)
                    acc[i][j] = fmaf(ar[i], br[j], acc[i][j]);
        }
        if (more) {
            buf ^= 1;
            sA[buf][kA + 0][rA] = na0.x; sA[buf][kA + 1][rA] = na0.y;
            sA[buf][kA + 2][rA] = na0.z; sA[buf][kA + 3][rA] = na0.w;
            sA[buf][kA + 0][rA + 64] = na1.x; sA[buf][kA + 1][rA + 64] = na1.y;
            sA[buf][kA + 2][rA + 64] = na1.z; sA[buf][kA + 3][rA + 64] = na1.w;
            *(float4*)&sB[buf][kB][cB]     = nb0;
            *(float4*)&sB[buf][kB + 8][cB] = nb1;
            __syncthreads();
        }
    }

    int rows[8], cols[8];
    #pragma unroll
    for (int i = 0; i < 4; ++i) {
        rows[i] = ty * 4 + i;   rows[i + 4] = 64 + ty * 4 + i;
        cols[i] = tx * 4 + i;   cols[i + 4] = 64 + tx * 4 + i;
    }

    if (MODE == 0 || MODE == 2) {
        #pragma unroll
        for (int ii = 0; ii < 8; ++ii) {
            const int gr = mBase + rows[ii];
            float sc = 1.f;
            if (MODE == 2) sc = g_ri[b * S + gr];
            float* crow = Cout + ((size_t)b * S + gr) * NDIM + nBase;
            float4 o0 = make_float4(acc[ii][0] * sc, acc[ii][1] * sc,
                                    acc[ii][2] * sc, acc[ii][3] * sc);
            float4 o1 = make_float4(acc[ii][4] * sc, acc[ii][5] * sc,
                                    acc[ii][6] * sc, acc[ii][7] * sc);
            *(float4*)(crow + tx * 4)      = o0;
            *(float4*)(crow + 64 + tx * 4) = o1;
        }
    } else {
        // MODE 1: dist -> weight, write W, accumulate row sums
        float v2loc[8];
        #pragma unroll
        for (int jj = 0; jj < 8; ++jj) v2loc[jj] = g_v2[b * S + nBase + cols[jj]];

        #pragma unroll
        for (int ii = 0; ii < 8; ++ii) {
            const int gr = mBase + rows[ii];
            const float m2v = g_m2[b * S + gr];
            const float* arow = Wsrc + ((size_t)b * S + gr) * S + nBase;
            float4 av0 = *(const float4*)(arow + tx * 4);
            float4 av1 = *(const float4*)(arow + 64 + tx * 4);
            float aval[8] = {av0.x, av0.y, av0.z, av0.w, av1.x, av1.y, av1.z, av1.w};
            float w[8];
            float rs = 0.f;
            #pragma unroll
            for (int jj = 0; jj < 8; ++jj) {
                float d2 = fmaxf(m2v + v2loc[jj] - 2.f * acc[ii][jj], 0.f);
                float dist = sqrtf(d2);
                float wv = __fdividef(aval[jj], dist + EPSI);
                w[jj] = wv;
                rs += fabsf(wv);
            }
            float* wrow = Cout + ((size_t)b * S + gr) * S + nBase;
            *(float4*)(wrow + tx * 4)      = make_float4(w[0], w[1], w[2], w[3]);
            *(float4*)(wrow + 64 + tx * 4) = make_float4(w[4], w[5], w[6], w[7]);
            sRed[rows[ii]][tx] = rs;
        }
        __syncthreads();
        if (tid < BM) {
            float s = 0.f;
            #pragma unroll
            for (int x = 0; x < 16; ++x) s += sRed[tid][x];
            g_rp[((size_t)(b * (S / BN) + blockIdx.x)) * S + mBase + tid] = s;
        }
    }
}

// ----------------- launch -----------------
extern "C" void kernel_launch(void* const* d_in, const int* in_sizes, int n_in,
                              void* d_out, int out_size) {
    const float* A = (const float*)d_in[0];
    const float* V = (const float*)d_in[1];
    float* out = (float*)d_out;

    void *pM, *pW, *pVt;
    cudaGetSymbolAddress(&pM,  g_M);
    cudaGetSymbolAddress(&pW,  g_W);
    cudaGetSymbolAddress(&pVt, g_Vt);
    void *pv2, *pm2;
    cudaGetSymbolAddress(&pv2, g_v2);
    cudaGetSymbolAddress(&pm2, g_m2);
    float* M  = (float*)pM;
    float* W  = (float*)pW;
    float* Vt = (float*)pVt;
    float* v2 = (float*)pv2;
    float* m2 = (float*)pm2;

    const int nrows = NB * S;

    // ||V_j||^2  (once)
    rownorm_kernel<<<(nrows * 32 + 255) / 256, 256>>>(V, v2, D, nrows);
    // V^T (once)
    transpose_kernel<<<dim3(D / 32, S / 32, NB), dim3(32, 8)>>>(V, Vt);
    // M = A @ V
    gemm_kernel<D, S, 0><<<dim3(D / BN, S / BM, NB), 256>>>(A, V, M, nullptr);

    for (int it = 0; it < 3; ++it) {
        rownorm_kernel<<<(nrows * 32 + 255) / 256, 256>>>(M, m2, D, nrows);
        // W = A / (cdist(M, V) + eps), plus per-tile row partial sums
        gemm_kernel<S, D, 1><<<dim3(S / BN, S / BM, NB), 256>>>(M, Vt, W, A);
        reduce_rinv_kernel<<<(NB * S + 255) / 256, 256>>>();
        // M = diag(1/l1) * (W @ V)
        float* dst = (it == 2) ? out : M;
        gemm_kernel<D, S, 2><<<dim3(D / BN, S / BM, NB), 256>>>(W, V, dst, nullptr);
    }
}

// round 4
// speedup vs baseline: 1.5532x; 1.5532x over previous
#include <cuda_runtime.h>
#include <cuda_bf16.h>
#include <cstdint>
#include <cstddef>

#define S 2048
#define D 512
#define NB 4
#define EPSI 0.01f
#define BK 32
#define SWZ(x) ((x) ^ (((x) >> 3) & 0x70))
#define SMEMB (65536 + 2048)

// ---------------- device scratch ----------------
__device__ __align__(128) float          g_M  [(size_t)NB * S * D];
__device__ __align__(128) __nv_bfloat16  g_Ah [(size_t)NB * S * S];
__device__ __align__(128) __nv_bfloat16  g_Al [(size_t)NB * S * S];
__device__ __align__(128) __nv_bfloat16  g_Wh [(size_t)NB * S * S];
__device__ __align__(128) __nv_bfloat16  g_Wl [(size_t)NB * S * S];
__device__ __align__(128) __nv_bfloat16  g_Mh [(size_t)NB * S * D];
__device__ __align__(128) __nv_bfloat16  g_Ml [(size_t)NB * S * D];
__device__ __align__(128) __nv_bfloat16  g_Vh [(size_t)NB * S * D];
__device__ __align__(128) __nv_bfloat16  g_Vl [(size_t)NB * S * D];
__device__ __align__(128) __nv_bfloat16  g_Vth[(size_t)NB * D * S];
__device__ __align__(128) __nv_bfloat16  g_Vtl[(size_t)NB * D * S];
__device__ __align__(128) float          g_rp [(size_t)NB * 16 * S];
__device__ float g_ri[NB * S];
__device__ float g_m2[NB * S];
__device__ float g_v2[NB * S];

// ---------------- PTX helpers (compute_103-safe only) ----------------
__device__ __forceinline__ uint32_t smem_u32(const void* p) {
    uint32_t a;
    asm("{ .reg .u64 t; cvta.to.shared.u64 t, %1; cvt.u32.u64 %0, t; }" : "=r"(a) : "l"(p));
    return a;
}
__device__ __forceinline__ void cpasync16(uint32_t smem, const void* g) {
    asm volatile("cp.async.cg.shared.global [%0], [%1], 16;" :: "r"(smem), "l"(g));
}
__device__ __forceinline__ void cp_commit() {
    asm volatile("cp.async.commit_group;" ::: "memory");
}
template <int N>
__device__ __forceinline__ void cp_wait() {
    asm volatile("cp.async.wait_group %0;" :: "n"(N) : "memory");
}
__device__ __forceinline__ void ldsm4(uint32_t* r, uint32_t addr) {
    asm volatile("ldmatrix.sync.aligned.m8n8.x4.shared.b16 {%0,%1,%2,%3}, [%4];"
                 : "=r"(r[0]), "=r"(r[1]), "=r"(r[2]), "=r"(r[3]) : "r"(addr));
}
__device__ __forceinline__ void mma_bf16(float* c, const uint32_t* a, uint32_t b0, uint32_t b1) {
    asm volatile("mma.sync.aligned.m16n8k16.row.col.f32.bf16.bf16.f32 "
                 "{%0,%1,%2,%3}, {%4,%5,%6,%7}, {%8,%9}, {%0,%1,%2,%3};"
                 : "+f"(c[0]), "+f"(c[1]), "+f"(c[2]), "+f"(c[3])
                 : "r"(a[0]), "r"(a[1]), "r"(a[2]), "r"(a[3]), "r"(b0), "r"(b1));
}
__device__ __forceinline__ unsigned pkb(__nv_bfloat16 a, __nv_bfloat16 b) {
    unsigned short ua = *(unsigned short*)&a, ub = *(unsigned short*)&b;
    return (unsigned)ua | ((unsigned)ub << 16);
}

// ---------------- small kernels ----------------
__global__ void rownorm_kernel(const float* __restrict__ X, float* __restrict__ out,
                               int cols, int nrows) {
    int warp = (blockIdx.x * blockDim.x + threadIdx.x) >> 5;
    int lane = threadIdx.x & 31;
    if (warp >= nrows) return;
    const float* row = X + (size_t)warp * cols;
    float s = 0.f;
    for (int c = lane * 4; c < cols; c += 128) {
        float4 v = *(const float4*)(row + c);
        s += v.x * v.x + v.y * v.y + v.z * v.z + v.w * v.w;
    }
    #pragma unroll
    for (int off = 16; off >= 1; off >>= 1) s += __shfl_xor_sync(0xffffffffu, s, off);
    if (lane == 0) out[warp] = s;
}

__global__ void convert_hilo_kernel(const float* __restrict__ X,
                                    __nv_bfloat16* __restrict__ H,
                                    __nv_bfloat16* __restrict__ L, size_t n) {
    size_t i = ((size_t)blockIdx.x * blockDim.x + threadIdx.x) * 4;
    if (i >= n) return;
    float4 v = *(const float4*)(X + i);
    __nv_bfloat16 h0 = __float2bfloat16(v.x), h1 = __float2bfloat16(v.y);
    __nv_bfloat16 h2 = __float2bfloat16(v.z), h3 = __float2bfloat16(v.w);
    float l0 = v.x - __bfloat162float(h0), l1 = v.y - __bfloat162float(h1);
    float l2 = v.z - __bfloat162float(h2), l3 = v.w - __bfloat162float(h3);
    *(uint2*)(H + i) = make_uint2(pkb(h0, h1), pkb(h2, h3));
    *(uint2*)(L + i) = make_uint2(pkb(__float2bfloat16(l0), __float2bfloat16(l1)),
                                  pkb(__float2bfloat16(l2), __float2bfloat16(l3)));
}

__global__ void transpose_hilo_kernel(const float* __restrict__ V,
                                      __nv_bfloat16* __restrict__ Th,
                                      __nv_bfloat16* __restrict__ Tl) {
    __shared__ float tile[32][33];
    int b = blockIdx.z, d0 = blockIdx.x * 32, j0 = blockIdx.y * 32;
    int tx = threadIdx.x, ty = threadIdx.y;
    #pragma unroll
    for (int r = 0; r < 32; r += 8)
        tile[ty + r][tx] = V[((size_t)b * S + j0 + ty + r) * D + d0 + tx];
    __syncthreads();
    #pragma unroll
    for (int r = 0; r < 32; r += 8) {
        float x = tile[tx][ty + r];
        __nv_bfloat16 h = __float2bfloat16(x);
        size_t o = ((size_t)b * D + d0 + ty + r) * S + j0 + tx;
        Th[o] = h;
        Tl[o] = __float2bfloat16(x - __bfloat162float(h));
    }
}

__global__ void reduce_rinv_kernel() {
    int idx = blockIdx.x * blockDim.x + threadIdx.x;
    if (idx >= NB * S) return;
    int b = idx / S, i = idx - b * S;
    float s = 0.f;
    #pragma unroll
    for (int t = 0; t < 16; ++t) s += g_rp[((size_t)(b * 16 + t)) * S + i];
    g_ri[idx] = 1.0f / fmaxf(s, 1e-12f);
}

// ---------------- HMMA GEMM: C[128,128] = sum_k A[128,k]*B[128,k]^T, bf16 3-split ----------------
// smem layout (dynamic): [0, 32KB) A tiles (2 bufs x 16KB), [32KB, 64KB) B tiles, [64KB, +2KB) red
// tile row = 128 bytes: [hi: 32 bf16 | lo: 32 bf16], SW128 swizzled.
template <int NDIM, int KDIM, int MODE>
__global__ void __launch_bounds__(256, 1)
tc_gemm(const __nv_bfloat16* __restrict__ Ah, const __nv_bfloat16* __restrict__ Al,
        const __nv_bfloat16* __restrict__ Bh, const __nv_bfloat16* __restrict__ Bl,
        float* __restrict__ dstF, __nv_bfloat16* __restrict__ dstH,
        __nv_bfloat16* __restrict__ dstL, const float* __restrict__ Ain) {
    extern __shared__ char dsm[];
    const uint32_t sb = smem_u32(dsm);
    float* red = (float*)(dsm + 65536);   // [128][4]

    const int b = blockIdx.z;
    const int mBase = blockIdx.y * 128;
    const int nBase = blockIdx.x * 128;
    const int tid = threadIdx.x;
    const int lane = tid & 31, wid = tid >> 5;
    const int wm = wid & 1, wn = wid >> 1;         // warp tile: M64 x N32

    // global load mapping: each thread loads row=tid>>1, two 16B quads per half
    const int grow_ld = tid >> 1;
    const int hsel = tid & 1;
    const __nv_bfloat16* pAh = Ah + (size_t)b * S * KDIM + (size_t)(mBase + grow_ld) * KDIM;
    const __nv_bfloat16* pAl = Al + (size_t)b * S * KDIM + (size_t)(mBase + grow_ld) * KDIM;
    const __nv_bfloat16* pBh = Bh + (size_t)b * NDIM * KDIM + (size_t)(nBase + grow_ld) * KDIM;
    const __nv_bfloat16* pBl = Bl + (size_t)b * NDIM * KDIM + (size_t)(nBase + grow_ld) * KDIM;

    const uint32_t rowb = (uint32_t)grow_ld * 128;

    auto load_chunk = [&](int t, int buf) {
        const int kb = t * BK;
        const uint32_t ab = sb + buf * 16384;
        const uint32_t bb = sb + 32768 + buf * 16384;
        #pragma unroll
        for (int j = 0; j < 2; ++j) {
            const int seg = hsel * 2 + j;
            cpasync16(ab + SWZ(rowb + seg * 16),      pAh + kb + seg * 8);
            cpasync16(ab + SWZ(rowb + 64 + seg * 16), pAl + kb + seg * 8);
            cpasync16(bb + SWZ(rowb + seg * 16),      pBh + kb + seg * 8);
            cpasync16(bb + SWZ(rowb + 64 + seg * 16), pBl + kb + seg * 8);
        }
        cp_commit();
    };

    float acc[4][4][4];
    #pragma unroll
    for (int i = 0; i < 4; ++i)
        #pragma unroll
        for (int j = 0; j < 4; ++j)
            #pragma unroll
            for (int e = 0; e < 4; ++e) acc[i][j][e] = 0.f;

    const int nT = KDIM / BK;
    load_chunk(0, 0);

    const int lrow = lane & 15, cseg = lane >> 4;

    for (int t = 0; t < nT; ++t) {
        const int buf = t & 1;
        if (t + 1 < nT) { load_chunk(t + 1, buf ^ 1); cp_wait<1>(); }
        else cp_wait<0>();
        __syncthreads();

        const uint32_t ab = sb + buf * 16384;
        const uint32_t bb = sb + 32768 + buf * 16384;

        #pragma unroll
        for (int s = 0; s < 2; ++s) {
            const uint32_t kcol = (uint32_t)(s * 2 + cseg) * 16;
            uint32_t bfh[2][4], bfl[2][4];
            #pragma unroll
            for (int g = 0; g < 2; ++g) {
                const uint32_t br = (uint32_t)(wn * 32 + g * 16 + lrow) * 128;
                ldsm4(bfh[g], bb + SWZ(br + kcol));
                ldsm4(bfl[g], bb + SWZ(br + 64 + kcol));
            }
            uint32_t afh[4][4], afl[4][4];
            #pragma unroll
            for (int mf = 0; mf < 4; ++mf) {
                const uint32_t arr = (uint32_t)(wm * 64 + mf * 16 + lrow) * 128;
                ldsm4(afh[mf], ab + SWZ(arr + kcol));
                ldsm4(afl[mf], ab + SWZ(arr + 64 + kcol));
            }
            #pragma unroll
            for (int mf = 0; mf < 4; ++mf)
                #pragma unroll
                for (int nf = 0; nf < 4; ++nf) {
                    const int g = nf >> 1, h = nf & 1;
                    mma_bf16(acc[mf][nf], afh[mf], bfh[g][h], bfh[g][h + 2]);
                    mma_bf16(acc[mf][nf], afh[mf], bfl[g][h], bfl[g][h + 2]);
                    mma_bf16(acc[mf][nf], afl[mf], bfh[g][h], bfh[g][h + 2]);
                }
        }
        __syncthreads();
    }

    // ---------------- epilogue ----------------
    const int q = lane >> 2, tq = lane & 3;

    if (MODE == 1) {
        float v2c[4][2];
        #pragma unroll
        for (int nf = 0; nf < 4; ++nf) {
            float2 v2v = *(const float2*)(g_v2 + b * S + nBase + wn * 32 + nf * 8 + tq * 2);
            v2c[nf][0] = v2v.x; v2c[nf][1] = v2v.y;
        }
        #pragma unroll
        for (int mf = 0; mf < 4; ++mf) {
            #pragma unroll
            for (int r2 = 0; r2 < 2; ++r2) {
                const int lr = wm * 64 + mf * 16 + q + r2 * 8;
                const int gr = mBase + lr;
                const float m2v = g_m2[b * S + gr];
                const float* arow = Ain + ((size_t)b * S + gr) * S + nBase + wn * 32;
                __nv_bfloat16* whp = dstH + ((size_t)b * S + gr) * S + nBase + wn * 32;
                __nv_bfloat16* wlp = dstL + ((size_t)b * S + gr) * S + nBase + wn * 32;
                float rs = 0.f;
                #pragma unroll
                for (int nf = 0; nf < 4; ++nf) {
                    float2 a2 = *(const float2*)(arow + nf * 8 + tq * 2);
                    float w0, w1;
                    {
                        float d2 = fmaxf(m2v + v2c[nf][0] - 2.f * acc[mf][nf][r2 * 2], 0.f);
                        w0 = __fdividef(a2.x, sqrtf(d2) + EPSI);
                        d2 = fmaxf(m2v + v2c[nf][1] - 2.f * acc[mf][nf][r2 * 2 + 1], 0.f);
                        w1 = __fdividef(a2.y, sqrtf(d2) + EPSI);
                    }
                    rs += fabsf(w0) + fabsf(w1);
                    __nv_bfloat16 h0 = __float2bfloat16(w0), h1 = __float2bfloat16(w1);
                    *(unsigned*)(whp + nf * 8 + tq * 2) = pkb(h0, h1);
                    *(unsigned*)(wlp + nf * 8 + tq * 2) =
                        pkb(__float2bfloat16(w0 - __bfloat162float(h0)),
                            __float2bfloat16(w1 - __bfloat162float(h1)));
                }
                rs += __shfl_xor_sync(0xffffffffu, rs, 1);
                rs += __shfl_xor_sync(0xffffffffu, rs, 2);
                if (tq == 0) red[lr * 4 + wn] = rs;
            }
        }
        __syncthreads();
        if (tid < 128) {
            float s = red[tid * 4] + red[tid * 4 + 1] + red[tid * 4 + 2] + red[tid * 4 + 3];
            g_rp[((size_t)(b * 16 + blockIdx.x)) * S + mBase + tid] = s;
        }
    } else {
        #pragma unroll
        for (int mf = 0; mf < 4; ++mf) {
            #pragma unroll
            for (int r2 = 0; r2 < 2; ++r2) {
                const int gr = mBase + wm * 64 + mf * 16 + q + r2 * 8;
                const float sc = (MODE == 2) ? g_ri[b * S + gr] : 1.f;
                float* fo = dstF + ((size_t)b * S + gr) * NDIM + nBase + wn * 32;
                __nv_bfloat16* hp = dstH + ((size_t)b * S + gr) * NDIM + nBase + wn * 32;
                __nv_bfloat16* lp = dstL + ((size_t)b * S + gr) * NDIM + nBase + wn * 32;
                #pragma unroll
                for (int nf = 0; nf < 4; ++nf) {
                    float o0 = acc[mf][nf][r2 * 2] * sc;
                    float o1 = acc[mf][nf][r2 * 2 + 1] * sc;
                    *(float2*)(fo + nf * 8 + tq * 2) = make_float2(o0, o1);
                    __nv_bfloat16 h0 = __float2bfloat16(o0), h1 = __float2bfloat16(o1);
                    *(unsigned*)(hp + nf * 8 + tq * 2) = pkb(h0, h1);
                    *(unsigned*)(lp + nf * 8 + tq * 2) =
                        pkb(__float2bfloat16(o0 - __bfloat162float(h0)),
                            __float2bfloat16(o1 - __bfloat162float(h1)));
                }
            }
        }
    }
}

// ---------------- launch ----------------
extern "C" void kernel_launch(void* const* d_in, const int* in_sizes, int n_in,
                              void* d_out, int out_size) {
    const float* A = (const float*)d_in[0];
    const float* V = (const float*)d_in[1];
    float* out = (float*)d_out;

    void* p;
    cudaGetSymbolAddress(&p, g_M);   float* M = (float*)p;
    cudaGetSymbolAddress(&p, g_Ah);  __nv_bfloat16* Ah = (__nv_bfloat16*)p;
    cudaGetSymbolAddress(&p, g_Al);  __nv_bfloat16* Al = (__nv_bfloat16*)p;
    cudaGetSymbolAddress(&p, g_Wh);  __nv_bfloat16* Wh = (__nv_bfloat16*)p;
    cudaGetSymbolAddress(&p, g_Wl);  __nv_bfloat16* Wl = (__nv_bfloat16*)p;
    cudaGetSymbolAddress(&p, g_Mh);  __nv_bfloat16* Mh = (__nv_bfloat16*)p;
    cudaGetSymbolAddress(&p, g_Ml);  __nv_bfloat16* Ml = (__nv_bfloat16*)p;
    cudaGetSymbolAddress(&p, g_Vh);  __nv_bfloat16* Vh = (__nv_bfloat16*)p;
    cudaGetSymbolAddress(&p, g_Vl);  __nv_bfloat16* Vl = (__nv_bfloat16*)p;
    cudaGetSymbolAddress(&p, g_Vth); __nv_bfloat16* Vth = (__nv_bfloat16*)p;
    cudaGetSymbolAddress(&p, g_Vtl); __nv_bfloat16* Vtl = (__nv_bfloat16*)p;
    cudaGetSymbolAddress(&p, g_v2);  float* v2 = (float*)p;
    cudaGetSymbolAddress(&p, g_m2);  float* m2 = (float*)p;

    cudaFuncSetAttribute(tc_gemm<D, S, 0>, cudaFuncAttributeMaxDynamicSharedMemorySize, SMEMB);
    cudaFuncSetAttribute(tc_gemm<S, D, 1>, cudaFuncAttributeMaxDynamicSharedMemorySize, SMEMB);
    cudaFuncSetAttribute(tc_gemm<D, S, 2>, cudaFuncAttributeMaxDynamicSharedMemorySize, SMEMB);

    const int nrows = NB * S;
    const size_t nA = (size_t)NB * S * S;
    const size_t nV = (size_t)NB * S * D;

    convert_hilo_kernel<<<(unsigned)((nA / 4 + 255) / 256), 256>>>(A, Ah, Al, nA);
    convert_hilo_kernel<<<(unsigned)((nV / 4 + 255) / 256), 256>>>(V, Vh, Vl, nV);
    transpose_hilo_kernel<<<dim3(D / 32, S / 32, NB), dim3(32, 8)>>>(V, Vth, Vtl);
    rownorm_kernel<<<(nrows * 32 + 255) / 256, 256>>>(V, v2, D, nrows);

    // M = A @ V  (B operand = V^T rows [D][S])
    tc_gemm<D, S, 0><<<dim3(D / 128, S / 128, NB), 256, SMEMB>>>(
        Ah, Al, Vth, Vtl, M, Mh, Ml, nullptr);

    for (int it = 0; it < 3; ++it) {
        rownorm_kernel<<<(nrows * 32 + 255) / 256, 256>>>(M, m2, D, nrows);
        // W = A / (cdist(M,V)+eps); dots via M·V^T (B operand = V rows [S][D])
        tc_gemm<S, D, 1><<<dim3(S / 128, S / 128, NB), 256, SMEMB>>>(
            Mh, Ml, Vh, Vl, nullptr, Wh, Wl, A);
        reduce_rinv_kernel<<<(NB * S + 255) / 256, 256>>>();
        // M = diag(1/l1) * (W @ V)
        float* dst = (it == 2) ? out : M;
        tc_gemm<D, S, 2><<<dim3(D / 128, S / 128, NB), 256, SMEMB>>>(
            Wh, Wl, Vth, Vtl, dst, Mh, Ml, nullptr);
    }
}

// round 5
// speedup vs baseline: 1.7577x; 1.1316x over previous
#include <cuda_runtime.h>
#include <cuda_bf16.h>
#include <cstdint>
#include <cstddef>

#define S 2048
#define D 512
#define NB 4
#define EPSI 0.01f
#define BK 32
#define STAGES 4
#define SWZ(x) ((x) ^ (((x) >> 3) & 0x70))
#define SMEMB (131072 + 2048)

// ---------------- device scratch ----------------
__device__ __align__(128) float          g_M  [(size_t)NB * S * D];
__device__ __align__(128) __nv_bfloat16  g_Ah [(size_t)NB * S * S];
__device__ __align__(128) __nv_bfloat16  g_Al [(size_t)NB * S * S];
__device__ __align__(128) __nv_bfloat16  g_Wh [(size_t)NB * S * S];
__device__ __align__(128) __nv_bfloat16  g_Wl [(size_t)NB * S * S];
__device__ __align__(128) __nv_bfloat16  g_Mh [(size_t)NB * S * D];
__device__ __align__(128) __nv_bfloat16  g_Ml [(size_t)NB * S * D];
__device__ __align__(128) __nv_bfloat16  g_Vh [(size_t)NB * S * D];
__device__ __align__(128) __nv_bfloat16  g_Vl [(size_t)NB * S * D];
__device__ __align__(128) __nv_bfloat16  g_Vth[(size_t)NB * D * S];
__device__ __align__(128) __nv_bfloat16  g_Vtl[(size_t)NB * D * S];
__device__ __align__(128) float          g_rp [(size_t)NB * 16 * S];
__device__ float g_ri[NB * S];
__device__ float g_m2[NB * S];
__device__ float g_v2[NB * S];

// ---------------- PTX helpers (compute_103-safe only) ----------------
__device__ __forceinline__ uint32_t smem_u32(const void* p) {
    uint32_t a;
    asm("{ .reg .u64 t; cvta.to.shared.u64 t, %1; cvt.u32.u64 %0, t; }" : "=r"(a) : "l"(p));
    return a;
}
__device__ __forceinline__ void cpasync16(uint32_t smem, const void* g) {
    asm volatile("cp.async.cg.shared.global [%0], [%1], 16;" :: "r"(smem), "l"(g));
}
__device__ __forceinline__ void cp_commit() {
    asm volatile("cp.async.commit_group;" ::: "memory");
}
template <int N>
__device__ __forceinline__ void cp_wait() {
    asm volatile("cp.async.wait_group %0;" :: "n"(N) : "memory");
}
__device__ __forceinline__ void ldsm4(uint32_t* r, uint32_t addr) {
    asm volatile("ldmatrix.sync.aligned.m8n8.x4.shared.b16 {%0,%1,%2,%3}, [%4];"
                 : "=r"(r[0]), "=r"(r[1]), "=r"(r[2]), "=r"(r[3]) : "r"(addr));
}
__device__ __forceinline__ void mma_bf16(float* c, const uint32_t* a, uint32_t b0, uint32_t b1) {
    asm volatile("mma.sync.aligned.m16n8k16.row.col.f32.bf16.bf16.f32 "
                 "{%0,%1,%2,%3}, {%4,%5,%6,%7}, {%8,%9}, {%0,%1,%2,%3};"
                 : "+f"(c[0]), "+f"(c[1]), "+f"(c[2]), "+f"(c[3])
                 : "r"(a[0]), "r"(a[1]), "r"(a[2]), "r"(a[3]), "r"(b0), "r"(b1));
}
__device__ __forceinline__ unsigned pkb(__nv_bfloat16 a, __nv_bfloat16 b) {
    unsigned short ua = *(unsigned short*)&a, ub = *(unsigned short*)&b;
    return (unsigned)ua | ((unsigned)ub << 16);
}

// ---------------- small kernels ----------------
__global__ void rownorm_kernel(const float* __restrict__ X, float* __restrict__ out,
                               int cols, int nrows) {
    int warp = (blockIdx.x * blockDim.x + threadIdx.x) >> 5;
    int lane = threadIdx.x & 31;
    if (warp >= nrows) return;
    const float* row = X + (size_t)warp * cols;
    float s = 0.f;
    for (int c = lane * 4; c < cols; c += 128) {
        float4 v = *(const float4*)(row + c);
        s += v.x * v.x + v.y * v.y + v.z * v.z + v.w * v.w;
    }
    #pragma unroll
    for (int off = 16; off >= 1; off >>= 1) s += __shfl_xor_sync(0xffffffffu, s, off);
    if (lane == 0) out[warp] = s;
}

__global__ void convert_hilo_kernel(const float* __restrict__ X,
                                    __nv_bfloat16* __restrict__ H,
                                    __nv_bfloat16* __restrict__ L, size_t n) {
    size_t i = ((size_t)blockIdx.x * blockDim.x + threadIdx.x) * 4;
    if (i >= n) return;
    float4 v = *(const float4*)(X + i);
    __nv_bfloat16 h0 = __float2bfloat16(v.x), h1 = __float2bfloat16(v.y);
    __nv_bfloat16 h2 = __float2bfloat16(v.z), h3 = __float2bfloat16(v.w);
    float l0 = v.x - __bfloat162float(h0), l1 = v.y - __bfloat162float(h1);
    float l2 = v.z - __bfloat162float(h2), l3 = v.w - __bfloat162float(h3);
    *(uint2*)(H + i) = make_uint2(pkb(h0, h1), pkb(h2, h3));
    *(uint2*)(L + i) = make_uint2(pkb(__float2bfloat16(l0), __float2bfloat16(l1)),
                                  pkb(__float2bfloat16(l2), __float2bfloat16(l3)));
}

__global__ void transpose_hilo_kernel(const float* __restrict__ V,
                                      __nv_bfloat16* __restrict__ Th,
                                      __nv_bfloat16* __restrict__ Tl) {
    __shared__ float tile[32][33];
    int b = blockIdx.z, d0 = blockIdx.x * 32, j0 = blockIdx.y * 32;
    int tx = threadIdx.x, ty = threadIdx.y;
    #pragma unroll
    for (int r = 0; r < 32; r += 8)
        tile[ty + r][tx] = V[((size_t)b * S + j0 + ty + r) * D + d0 + tx];
    __syncthreads();
    #pragma unroll
    for (int r = 0; r < 32; r += 8) {
        float x = tile[tx][ty + r];
        __nv_bfloat16 h = __float2bfloat16(x);
        size_t o = ((size_t)b * D + d0 + ty + r) * S + j0 + tx;
        Th[o] = h;
        Tl[o] = __float2bfloat16(x - __bfloat162float(h));
    }
}

__global__ void reduce_rinv_kernel() {
    int idx = blockIdx.x * blockDim.x + threadIdx.x;
    if (idx >= NB * S) return;
    int b = idx / S, i = idx - b * S;
    float s = 0.f;
    #pragma unroll
    for (int t = 0; t < 16; ++t) s += g_rp[((size_t)(b * 16 + t)) * S + i];
    g_ri[idx] = 1.0f / fmaxf(s, 1e-12f);
}

// ---------------- HMMA GEMM: C[128,128] = sum_k A[128,k]*B[128,k]^T ----------------
// NPROD=3: ah*bh + ah*bl + al*bh.  NPROD=2: ah*bh + al*bh (A-side exact; B lo not loaded).
// smem: STAGES x (A 16KB @ sb + st*16K | B 16KB @ sb + 64K + st*16K); red at +128K.
// tile row = 128 bytes: [hi: 32 bf16 | lo: 32 bf16], SW128 swizzled.
template <int NDIM, int KDIM, int MODE, int NPROD>
__global__ void __launch_bounds__(256, 1)
tc_gemm(const __nv_bfloat16* __restrict__ Ah, const __nv_bfloat16* __restrict__ Al,
        const __nv_bfloat16* __restrict__ Bh, const __nv_bfloat16* __restrict__ Bl,
        float* __restrict__ dstF, __nv_bfloat16* __restrict__ dstH,
        __nv_bfloat16* __restrict__ dstL, const float* __restrict__ Ain) {
    extern __shared__ char dsm[];
    const uint32_t sb = smem_u32(dsm);
    float* red = (float*)(dsm + 131072);   // [128][4]

    const int b = blockIdx.z;
    const int mBase = blockIdx.y * 128;
    const int nBase = blockIdx.x * 128;
    const int tid = threadIdx.x;
    const int lane = tid & 31, wid = tid >> 5;
    const int wm = wid & 1, wn = wid >> 1;         // warp tile: M64 x N32

    const int grow_ld = tid >> 1;
    const int hsel = tid & 1;
    const __nv_bfloat16* pAh = Ah + (size_t)b * S * KDIM + (size_t)(mBase + grow_ld) * KDIM;
    const __nv_bfloat16* pAl = Al + (size_t)b * S * KDIM + (size_t)(mBase + grow_ld) * KDIM;
    const __nv_bfloat16* pBh = Bh + (size_t)b * NDIM * KDIM + (size_t)(nBase + grow_ld) * KDIM;
    const __nv_bfloat16* pBl = Bl + (size_t)b * NDIM * KDIM + (size_t)(nBase + grow_ld) * KDIM;

    const uint32_t rowb = (uint32_t)grow_ld * 128;
    const int nT = KDIM / BK;

    auto load_chunk = [&](int t, int stage) {
        if (t < nT) {
            const int kb = t * BK;
            const uint32_t ab = sb + stage * 16384;
            const uint32_t bb = sb + 65536 + stage * 16384;
            #pragma unroll
            for (int j = 0; j < 2; ++j) {
                const int seg = hsel * 2 + j;
                cpasync16(ab + SWZ(rowb + seg * 16),      pAh + kb + seg * 8);
                cpasync16(ab + SWZ(rowb + 64 + seg * 16), pAl + kb + seg * 8);
                cpasync16(bb + SWZ(rowb + seg * 16),      pBh + kb + seg * 8);
                if (NPROD == 3)
                    cpasync16(bb + SWZ(rowb + 64 + seg * 16), pBl + kb + seg * 8);
            }
        }
        cp_commit();
    };

    float acc[4][4][4];
    #pragma unroll
    for (int i = 0; i < 4; ++i)
        #pragma unroll
        for (int j = 0; j < 4; ++j)
            #pragma unroll
            for (int e = 0; e < 4; ++e) acc[i][j][e] = 0.f;

    // prologue: stages 0..STAGES-2
    load_chunk(0, 0);
    load_chunk(1, 1);
    load_chunk(2, 2);

    const int lrow = lane & 15, cseg = lane >> 4;

    for (int t = 0; t < nT; ++t) {
        cp_wait<STAGES - 2>();
        __syncthreads();
        load_chunk(t + STAGES - 1, (t + STAGES - 1) & (STAGES - 1));

        const int buf = t & (STAGES - 1);
        const uint32_t ab = sb + buf * 16384;
        const uint32_t bb = sb + 65536 + buf * 16384;

        #pragma unroll
        for (int s = 0; s < 2; ++s) {
            const uint32_t kcol = (uint32_t)(s * 2 + cseg) * 16;
            uint32_t bfh[2][4], bfl[2][4];
            #pragma unroll
            for (int g = 0; g < 2; ++g) {
                const uint32_t br = (uint32_t)(wn * 32 + g * 16 + lrow) * 128;
                ldsm4(bfh[g], bb + SWZ(br + kcol));
                if (NPROD == 3) ldsm4(bfl[g], bb + SWZ(br + 64 + kcol));
            }
            uint32_t afh[4][4], afl[4][4];
            #pragma unroll
            for (int mf = 0; mf < 4; ++mf) {
                const uint32_t arr = (uint32_t)(wm * 64 + mf * 16 + lrow) * 128;
                ldsm4(afh[mf], ab + SWZ(arr + kcol));
                ldsm4(afl[mf], ab + SWZ(arr + 64 + kcol));
            }
            #pragma unroll
            for (int mf = 0; mf < 4; ++mf)
                #pragma unroll
                for (int nf = 0; nf < 4; ++nf) {
                    const int g = nf >> 1, h = nf & 1;
                    mma_bf16(acc[mf][nf], afh[mf], bfh[g][h], bfh[g][h + 2]);
                    if (NPROD == 3)
                        mma_bf16(acc[mf][nf], afh[mf], bfl[g][h], bfl[g][h + 2]);
                    mma_bf16(acc[mf][nf], afl[mf], bfh[g][h], bfh[g][h + 2]);
                }
        }
    }

    // ---------------- epilogue ----------------
    const int q = lane >> 2, tq = lane & 3;

    if (MODE == 1) {
        float v2c[4][2];
        #pragma unroll
        for (int nf = 0; nf < 4; ++nf) {
            float2 v2v = *(const float2*)(g_v2 + b * S + nBase + wn * 32 + nf * 8 + tq * 2);
            v2c[nf][0] = v2v.x; v2c[nf][1] = v2v.y;
        }
        #pragma unroll
        for (int mf = 0; mf < 4; ++mf) {
            #pragma unroll
            for (int r2 = 0; r2 < 2; ++r2) {
                const int lr = wm * 64 + mf * 16 + q + r2 * 8;
                const int gr = mBase + lr;
                const float m2v = g_m2[b * S + gr];
                const float* arow = Ain + ((size_t)b * S + gr) * S + nBase + wn * 32;
                __nv_bfloat16* whp = dstH + ((size_t)b * S + gr) * S + nBase + wn * 32;
                __nv_bfloat16* wlp = dstL + ((size_t)b * S + gr) * S + nBase + wn * 32;
                float rs = 0.f;
                #pragma unroll
                for (int nf = 0; nf < 4; ++nf) {
                    float2 a2 = *(const float2*)(arow + nf * 8 + tq * 2);
                    float w0, w1;
                    {
                        float d2 = fmaxf(m2v + v2c[nf][0] - 2.f * acc[mf][nf][r2 * 2], 0.f);
                        w0 = __fdividef(a2.x, sqrtf(d2) + EPSI);
                        d2 = fmaxf(m2v + v2c[nf][1] - 2.f * acc[mf][nf][r2 * 2 + 1], 0.f);
                        w1 = __fdividef(a2.y, sqrtf(d2) + EPSI);
                    }
                    rs += fabsf(w0) + fabsf(w1);
                    __nv_bfloat16 h0 = __float2bfloat16(w0), h1 = __float2bfloat16(w1);
                    *(unsigned*)(whp + nf * 8 + tq * 2) = pkb(h0, h1);
                    *(unsigned*)(wlp + nf * 8 + tq * 2) =
                        pkb(__float2bfloat16(w0 - __bfloat162float(h0)),
                            __float2bfloat16(w1 - __bfloat162float(h1)));
                }
                rs += __shfl_xor_sync(0xffffffffu, rs, 1);
                rs += __shfl_xor_sync(0xffffffffu, rs, 2);
                if (tq == 0) red[lr * 4 + wn] = rs;
            }
        }
        __syncthreads();
        if (tid < 128) {
            float s = red[tid * 4] + red[tid * 4 + 1] + red[tid * 4 + 2] + red[tid * 4 + 3];
            g_rp[((size_t)(b * 16 + blockIdx.x)) * S + mBase + tid] = s;
        }
    } else {
        #pragma unroll
        for (int mf = 0; mf < 4; ++mf) {
            #pragma unroll
            for (int r2 = 0; r2 < 2; ++r2) {
                const int gr = mBase + wm * 64 + mf * 16 + q + r2 * 8;
                const float sc = (MODE == 2) ? g_ri[b * S + gr] : 1.f;
                float* fo = dstF + ((size_t)b * S + gr) * NDIM + nBase + wn * 32;
                __nv_bfloat16* hp = dstH + ((size_t)b * S + gr) * NDIM + nBase + wn * 32;
                __nv_bfloat16* lp = dstL + ((size_t)b * S + gr) * NDIM + nBase + wn * 32;
                #pragma unroll
                for (int nf = 0; nf < 4; ++nf) {
                    float o0 = acc[mf][nf][r2 * 2] * sc;
                    float o1 = acc[mf][nf][r2 * 2 + 1] * sc;
                    *(float2*)(fo + nf * 8 + tq * 2) = make_float2(o0, o1);
                    __nv_bfloat16 h0 = __float2bfloat16(o0), h1 = __float2bfloat16(o1);
                    *(unsigned*)(hp + nf * 8 + tq * 2) = pkb(h0, h1);
                    *(unsigned*)(lp + nf * 8 + tq * 2) =
                        pkb(__float2bfloat16(o0 - __bfloat162float(h0)),
                            __float2bfloat16(o1 - __bfloat162float(h1)));
                }
            }
        }
    }
}

// ---------------- launch ----------------
extern "C" void kernel_launch(void* const* d_in, const int* in_sizes, int n_in,
                              void* d_out, int out_size) {
    const float* A = (const float*)d_in[0];
    const float* V = (const float*)d_in[1];
    float* out = (float*)d_out;

    void* p;
    cudaGetSymbolAddress(&p, g_M);   float* M = (float*)p;
    cudaGetSymbolAddress(&p, g_Ah);  __nv_bfloat16* Ah = (__nv_bfloat16*)p;
    cudaGetSymbolAddress(&p, g_Al);  __nv_bfloat16* Al = (__nv_bfloat16*)p;
    cudaGetSymbolAddress(&p, g_Wh);  __nv_bfloat16* Wh = (__nv_bfloat16*)p;
    cudaGetSymbolAddress(&p, g_Wl);  __nv_bfloat16* Wl = (__nv_bfloat16*)p;
    cudaGetSymbolAddress(&p, g_Mh);  __nv_bfloat16* Mh = (__nv_bfloat16*)p;
    cudaGetSymbolAddress(&p, g_Ml);  __nv_bfloat16* Ml = (__nv_bfloat16*)p;
    cudaGetSymbolAddress(&p, g_Vh);  __nv_bfloat16* Vh = (__nv_bfloat16*)p;
    cudaGetSymbolAddress(&p, g_Vl);  __nv_bfloat16* Vl = (__nv_bfloat16*)p;
    cudaGetSymbolAddress(&p, g_Vth); __nv_bfloat16* Vth = (__nv_bfloat16*)p;
    cudaGetSymbolAddress(&p, g_Vtl); __nv_bfloat16* Vtl = (__nv_bfloat16*)p;
    cudaGetSymbolAddress(&p, g_v2);  float* v2 = (float*)p;
    cudaGetSymbolAddress(&p, g_m2);  float* m2 = (float*)p;

    cudaFuncSetAttribute(tc_gemm<D, S, 0, 3>, cudaFuncAttributeMaxDynamicSharedMemorySize, SMEMB);
    cudaFuncSetAttribute(tc_gemm<S, D, 1, 2>, cudaFuncAttributeMaxDynamicSharedMemorySize, SMEMB);
    cudaFuncSetAttribute(tc_gemm<D, S, 2, 3>, cudaFuncAttributeMaxDynamicSharedMemorySize, SMEMB);

    const int nrows = NB * S;
    const size_t nA = (size_t)NB * S * S;
    const size_t nV = (size_t)NB * S * D;

    convert_hilo_kernel<<<(unsigned)((nA / 4 + 255) / 256), 256>>>(A, Ah, Al, nA);
    convert_hilo_kernel<<<(unsigned)((nV / 4 + 255) / 256), 256>>>(V, Vh, Vl, nV);
    transpose_hilo_kernel<<<dim3(D / 32, S / 32, NB), dim3(32, 8)>>>(V, Vth, Vtl);
    rownorm_kernel<<<(nrows * 32 + 255) / 256, 256>>>(V, v2, D, nrows);

    // M = A @ V  (B operand = V^T rows [D][S])
    tc_gemm<D, S, 0, 3><<<dim3(D / 128, S / 128, NB), 256, SMEMB>>>(
        Ah, Al, Vth, Vtl, M, Mh, Ml, nullptr);

    for (int it = 0; it < 3; ++it) {
        rownorm_kernel<<<(nrows * 32 + 255) / 256, 256>>>(M, m2, D, nrows);
        // W = A / (cdist(M,V)+eps); dots via M·V^T (B operand = V rows [S][D]); 2-product
        tc_gemm<S, D, 1, 2><<<dim3(S / 128, S / 128, NB), 256, SMEMB>>>(
            Mh, Ml, Vh, Vl, nullptr, Wh, Wl, A);
        reduce_rinv_kernel<<<(NB * S + 255) / 256, 256>>>();
        // M = diag(1/l1) * (W @ V); 3-product
        float* dst = (it == 2) ? out : M;
        tc_gemm<D, S, 2, 3><<<dim3(D / 128, S / 128, NB), 256, SMEMB>>>(
            Wh, Wl, Vth, Vtl, dst, Mh, Ml, nullptr);
    }
}

// round 6
// speedup vs baseline: 2.7641x; 1.5726x over previous
#include <cuda_runtime.h>
#include <cuda_bf16.h>
#include <cstdint>
#include <cstddef>

#define S 2048
#define D 512
#define NB 4
#define EPSI 0.01f
#define STAGES 4
#define SWZ(x) ((x) ^ (((x) >> 3) & 0x70))
#define SMEMB (131072 + 2048)

// ---------------- device scratch ----------------
__device__ __align__(128) float          g_M  [(size_t)NB * S * D];
__device__ __align__(128) __nv_bfloat16  g_Ah [(size_t)NB * S * S];
__device__ __align__(128) __nv_bfloat16  g_Wh [(size_t)NB * S * S];
__device__ __align__(128) __nv_bfloat16  g_Wl [(size_t)NB * S * S];
__device__ __align__(128) __nv_bfloat16  g_Mh [(size_t)NB * S * D];
__device__ __align__(128) __nv_bfloat16  g_Vh [(size_t)NB * S * D];
__device__ __align__(128) __nv_bfloat16  g_Vth[(size_t)NB * D * S];
__device__ __align__(128) __nv_bfloat16  g_Vtl[(size_t)NB * D * S];
__device__ __align__(128) float          g_rp [(size_t)NB * 16 * S];
__device__ float g_ri[NB * S];
__device__ float g_m2[NB * S];
__device__ float g_v2[NB * S];

// ---------------- PTX helpers (compute_103-safe only) ----------------
__device__ __forceinline__ uint32_t smem_u32(const void* p) {
    uint32_t a;
    asm("{ .reg .u64 t; cvta.to.shared.u64 t, %1; cvt.u32.u64 %0, t; }" : "=r"(a) : "l"(p));
    return a;
}
__device__ __forceinline__ void cpasync16(uint32_t smem, const void* g) {
    asm volatile("cp.async.cg.shared.global [%0], [%1], 16;" :: "r"(smem), "l"(g));
}
__device__ __forceinline__ void cp_commit() {
    asm volatile("cp.async.commit_group;" ::: "memory");
}
template <int N>
__device__ __forceinline__ void cp_wait() {
    asm volatile("cp.async.wait_group %0;" :: "n"(N) : "memory");
}
__device__ __forceinline__ void ldsm4(uint32_t* r, uint32_t addr) {
    asm volatile("ldmatrix.sync.aligned.m8n8.x4.shared.b16 {%0,%1,%2,%3}, [%4];"
                 : "=r"(r[0]), "=r"(r[1]), "=r"(r[2]), "=r"(r[3]) : "r"(addr));
}
__device__ __forceinline__ void mma_bf16(float* c, const uint32_t* a, uint32_t b0, uint32_t b1) {
    asm volatile("mma.sync.aligned.m16n8k16.row.col.f32.bf16.bf16.f32 "
                 "{%0,%1,%2,%3}, {%4,%5,%6,%7}, {%8,%9}, {%0,%1,%2,%3};"
                 : "+f"(c[0]), "+f"(c[1]), "+f"(c[2]), "+f"(c[3])
                 : "r"(a[0]), "r"(a[1]), "r"(a[2]), "r"(a[3]), "r"(b0), "r"(b1));
}
__device__ __forceinline__ unsigned pkb(__nv_bfloat16 a, __nv_bfloat16 b) {
    unsigned short ua = *(unsigned short*)&a, ub = *(unsigned short*)&b;
    return (unsigned)ua | ((unsigned)ub << 16);
}

// ---------------- small kernels ----------------
__global__ void rownorm_kernel(const float* __restrict__ X, float* __restrict__ out,
                               int cols, int nrows) {
    int warp = (blockIdx.x * blockDim.x + threadIdx.x) >> 5;
    int lane = threadIdx.x & 31;
    if (warp >= nrows) return;
    const float* row = X + (size_t)warp * cols;
    float s = 0.f;
    for (int c = lane * 4; c < cols; c += 128) {
        float4 v = *(const float4*)(row + c);
        s += v.x * v.x + v.y * v.y + v.z * v.z + v.w * v.w;
    }
    #pragma unroll
    for (int off = 16; off >= 1; off >>= 1) s += __shfl_xor_sync(0xffffffffu, s, off);
    if (lane == 0) out[warp] = s;
}

__global__ void convert_hi_kernel(const float* __restrict__ X,
                                  __nv_bfloat16* __restrict__ H, size_t n) {
    size_t i = ((size_t)blockIdx.x * blockDim.x + threadIdx.x) * 4;
    if (i >= n) return;
    float4 v = *(const float4*)(X + i);
    *(uint2*)(H + i) = make_uint2(pkb(__float2bfloat16(v.x), __float2bfloat16(v.y)),
                                  pkb(__float2bfloat16(v.z), __float2bfloat16(v.w)));
}

__global__ void transpose_hilo_kernel(const float* __restrict__ V,
                                      __nv_bfloat16* __restrict__ Th,
                                      __nv_bfloat16* __restrict__ Tl) {
    __shared__ float tile[32][33];
    int b = blockIdx.z, d0 = blockIdx.x * 32, j0 = blockIdx.y * 32;
    int tx = threadIdx.x, ty = threadIdx.y;
    #pragma unroll
    for (int r = 0; r < 32; r += 8)
        tile[ty + r][tx] = V[((size_t)b * S + j0 + ty + r) * D + d0 + tx];
    __syncthreads();
    #pragma unroll
    for (int r = 0; r < 32; r += 8) {
        float x = tile[tx][ty + r];
        __nv_bfloat16 h = __float2bfloat16(x);
        size_t o = ((size_t)b * D + d0 + ty + r) * S + j0 + tx;
        Th[o] = h;
        Tl[o] = __float2bfloat16(x - __bfloat162float(h));
    }
}

__global__ void reduce_rinv_kernel() {
    int idx = blockIdx.x * blockDim.x + threadIdx.x;
    if (idx >= NB * S) return;
    int b = idx / S, i = idx - b * S;
    float s = 0.f;
    #pragma unroll
    for (int t = 0; t < 16; ++t) s += g_rp[((size_t)(b * 16 + t)) * S + i];
    g_ri[idx] = 1.0f / fmaxf(s, 1e-12f);
}

// ---------------- HMMA GEMM: C[128,128] = sum_k A[128,k]*B[128,k]^T ----------------
// NPROD=3: BK=32, tile rows [hi 32 bf16 | lo 32 bf16] (128B), products ah*bh+ah*bl+al*bh.
// NPROD=1: BK=64, tile rows 64 bf16 hi-only (128B), product ah*bh.
// smem: STAGES x (A 16KB | B 16KB); red at +128K.
// MODE 0: store fp32 dstF (+ bf16 dstH if WLO).  MODE 1: weight epilogue -> Wh (+Wl if WLO) + row sums.
// MODE 2: row-scale, store fp32 dstF (+ dstH if WLO).
template <int NDIM, int KDIM, int MODE, int NPROD, bool WLO>
__global__ void __launch_bounds__(256, 1)
tc_gemm(const __nv_bfloat16* __restrict__ Ah, const __nv_bfloat16* __restrict__ Al,
        const __nv_bfloat16* __restrict__ Bh, const __nv_bfloat16* __restrict__ Bl,
        float* __restrict__ dstF, __nv_bfloat16* __restrict__ dstH,
        __nv_bfloat16* __restrict__ dstL, const float* __restrict__ Ain) {
    constexpr int BKL = (NPROD == 1) ? 64 : 32;
    constexpr int SST = BKL / 16;           // s-steps per chunk (4 or 2)
    extern __shared__ char dsm[];
    const uint32_t sb = smem_u32(dsm);
    float* red = (float*)(dsm + 131072);   // [128][4]

    const int b = blockIdx.z;
    const int mBase = blockIdx.y * 128;
    const int nBase = blockIdx.x * 128;
    const int tid = threadIdx.x;
    const int lane = tid & 31, wid = tid >> 5;
    const int wm = wid & 1, wn = wid >> 1;         // warp tile: M64 x N32

    const int grow_ld = tid >> 1;
    const int hsel = tid & 1;
    const __nv_bfloat16* pAh = Ah + (size_t)b * S * KDIM + (size_t)(mBase + grow_ld) * KDIM;
    const __nv_bfloat16* pAl = (NPROD == 3) ? Al + (size_t)b * S * KDIM + (size_t)(mBase + grow_ld) * KDIM : nullptr;
    const __nv_bfloat16* pBh = Bh + (size_t)b * NDIM * KDIM + (size_t)(nBase + grow_ld) * KDIM;
    const __nv_bfloat16* pBl = (NPROD == 3) ? Bl + (size_t)b * NDIM * KDIM + (size_t)(nBase + grow_ld) * KDIM : nullptr;

    const uint32_t rowb = (uint32_t)grow_ld * 128;
    const int nT = KDIM / BKL;

    auto load_chunk = [&](int t, int stage) {
        if (t < nT) {
            const int kb = t * BKL;
            const uint32_t ab = sb + stage * 16384;
            const uint32_t bb = sb + 65536 + stage * 16384;
            if (NPROD == 3) {
                #pragma unroll
                for (int j = 0; j < 2; ++j) {
                    const int seg = hsel * 2 + j;
                    cpasync16(ab + SWZ(rowb + seg * 16),      pAh + kb + seg * 8);
                    cpasync16(ab + SWZ(rowb + 64 + seg * 16), pAl + kb + seg * 8);
                    cpasync16(bb + SWZ(rowb + seg * 16),      pBh + kb + seg * 8);
                    cpasync16(bb + SWZ(rowb + 64 + seg * 16), pBl + kb + seg * 8);
                }
            } else {
                #pragma unroll
                for (int j = 0; j < 4; ++j) {
                    const int seg = hsel * 4 + j;
                    cpasync16(ab + SWZ(rowb + seg * 16), pAh + kb + seg * 8);
                    cpasync16(bb + SWZ(rowb + seg * 16), pBh + kb + seg * 8);
                }
            }
        }
        cp_commit();
    };

    float acc[4][4][4];
    #pragma unroll
    for (int i = 0; i < 4; ++i)
        #pragma unroll
        for (int j = 0; j < 4; ++j)
            #pragma unroll
            for (int e = 0; e < 4; ++e) acc[i][j][e] = 0.f;

    load_chunk(0, 0);
    load_chunk(1, 1);
    load_chunk(2, 2);

    const int lrow = lane & 15, cseg = lane >> 4;

    for (int t = 0; t < nT; ++t) {
        cp_wait<STAGES - 2>();
        __syncthreads();
        load_chunk(t + STAGES - 1, (t + STAGES - 1) & (STAGES - 1));

        const int buf = t & (STAGES - 1);
        const uint32_t ab = sb + buf * 16384;
        const uint32_t bb = sb + 65536 + buf * 16384;

        #pragma unroll
        for (int s = 0; s < SST; ++s) {
            const uint32_t kcol = (uint32_t)(s * 2 + cseg) * 16;
            uint32_t bfh[2][4], bfl[2][4];
            #pragma unroll
            for (int g = 0; g < 2; ++g) {
                const uint32_t br = (uint32_t)(wn * 32 + g * 16 + lrow) * 128;
                ldsm4(bfh[g], bb + SWZ(br + kcol));
                if (NPROD == 3) ldsm4(bfl[g], bb + SWZ(br + 64 + kcol));
            }
            uint32_t afh[4][4], afl[4][4];
            #pragma unroll
            for (int mf = 0; mf < 4; ++mf) {
                const uint32_t arr = (uint32_t)(wm * 64 + mf * 16 + lrow) * 128;
                ldsm4(afh[mf], ab + SWZ(arr + kcol));
                if (NPROD == 3) ldsm4(afl[mf], ab + SWZ(arr + 64 + kcol));
            }
            #pragma unroll
            for (int mf = 0; mf < 4; ++mf)
                #pragma unroll
                for (int nf = 0; nf < 4; ++nf) {
                    const int g = nf >> 1, h = nf & 1;
                    mma_bf16(acc[mf][nf], afh[mf], bfh[g][h], bfh[g][h + 2]);
                    if (NPROD == 3) {
                        mma_bf16(acc[mf][nf], afh[mf], bfl[g][h], bfl[g][h + 2]);
                        mma_bf16(acc[mf][nf], afl[mf], bfh[g][h], bfh[g][h + 2]);
                    }
                }
        }
    }

    // ---------------- epilogue ----------------
    const int q = lane >> 2, tq = lane & 3;

    if (MODE == 1) {
        float v2c[4][2];
        #pragma unroll
        for (int nf = 0; nf < 4; ++nf) {
            float2 v2v = *(const float2*)(g_v2 + b * S + nBase + wn * 32 + nf * 8 + tq * 2);
            v2c[nf][0] = v2v.x; v2c[nf][1] = v2v.y;
        }
        #pragma unroll
        for (int mf = 0; mf < 4; ++mf) {
            #pragma unroll
            for (int r2 = 0; r2 < 2; ++r2) {
                const int lr = wm * 64 + mf * 16 + q + r2 * 8;
                const int gr = mBase + lr;
                const float m2v = g_m2[b * S + gr];
                const float* arow = Ain + ((size_t)b * S + gr) * S + nBase + wn * 32;
                __nv_bfloat16* whp = dstH + ((size_t)b * S + gr) * S + nBase + wn * 32;
                __nv_bfloat16* wlp = WLO ? dstL + ((size_t)b * S + gr) * S + nBase + wn * 32 : nullptr;
                float rs = 0.f;
                #pragma unroll
                for (int nf = 0; nf < 4; ++nf) {
                    float2 a2 = *(const float2*)(arow + nf * 8 + tq * 2);
                    float w0, w1;
                    {
                        float d2 = fmaxf(m2v + v2c[nf][0] - 2.f * acc[mf][nf][r2 * 2], 0.f);
                        w0 = __fdividef(a2.x, sqrtf(d2) + EPSI);
                        d2 = fmaxf(m2v + v2c[nf][1] - 2.f * acc[mf][nf][r2 * 2 + 1], 0.f);
                        w1 = __fdividef(a2.y, sqrtf(d2) + EPSI);
                    }
                    rs += fabsf(w0) + fabsf(w1);
                    __nv_bfloat16 h0 = __float2bfloat16(w0), h1 = __float2bfloat16(w1);
                    *(unsigned*)(whp + nf * 8 + tq * 2) = pkb(h0, h1);
                    if (WLO)
                        *(unsigned*)(wlp + nf * 8 + tq * 2) =
                            pkb(__float2bfloat16(w0 - __bfloat162float(h0)),
                                __float2bfloat16(w1 - __bfloat162float(h1)));
                }
                rs += __shfl_xor_sync(0xffffffffu, rs, 1);
                rs += __shfl_xor_sync(0xffffffffu, rs, 2);
                if (tq == 0) red[lr * 4 + wn] = rs;
            }
        }
        __syncthreads();
        if (tid < 128) {
            float s = red[tid * 4] + red[tid * 4 + 1] + red[tid * 4 + 2] + red[tid * 4 + 3];
            g_rp[((size_t)(b * 16 + blockIdx.x)) * S + mBase + tid] = s;
        }
    } else {
        #pragma unroll
        for (int mf = 0; mf < 4; ++mf) {
            #pragma unroll
            for (int r2 = 0; r2 < 2; ++r2) {
                const int gr = mBase + wm * 64 + mf * 16 + q + r2 * 8;
                const float sc = (MODE == 2) ? g_ri[b * S + gr] : 1.f;
                float* fo = dstF + ((size_t)b * S + gr) * NDIM + nBase + wn * 32;
                __nv_bfloat16* hp = WLO ? dstH + ((size_t)b * S + gr) * NDIM + nBase + wn * 32 : nullptr;
                #pragma unroll
                for (int nf = 0; nf < 4; ++nf) {
                    float o0 = acc[mf][nf][r2 * 2] * sc;
                    float o1 = acc[mf][nf][r2 * 2 + 1] * sc;
                    *(float2*)(fo + nf * 8 + tq * 2) = make_float2(o0, o1);
                    if (WLO)
                        *(unsigned*)(hp + nf * 8 + tq * 2) =
                            pkb(__float2bfloat16(o0), __float2bfloat16(o1));
                }
            }
        }
    }
}

// ---------------- launch ----------------
extern "C" void kernel_launch(void* const* d_in, const int* in_sizes, int n_in,
                              void* d_out, int out_size) {
    const float* A = (const float*)d_in[0];
    const float* V = (const float*)d_in[1];
    float* out = (float*)d_out;

    void* p;
    cudaGetSymbolAddress(&p, g_M);   float* M = (float*)p;
    cudaGetSymbolAddress(&p, g_Ah);  __nv_bfloat16* Ah = (__nv_bfloat16*)p;
    cudaGetSymbolAddress(&p, g_Wh);  __nv_bfloat16* Wh = (__nv_bfloat16*)p;
    cudaGetSymbolAddress(&p, g_Wl);  __nv_bfloat16* Wl = (__nv_bfloat16*)p;
    cudaGetSymbolAddress(&p, g_Mh);  __nv_bfloat16* Mh = (__nv_bfloat16*)p;
    cudaGetSymbolAddress(&p, g_Vh);  __nv_bfloat16* Vh = (__nv_bfloat16*)p;
    cudaGetSymbolAddress(&p, g_Vth); __nv_bfloat16* Vth = (__nv_bfloat16*)p;
    cudaGetSymbolAddress(&p, g_Vtl); __nv_bfloat16* Vtl = (__nv_bfloat16*)p;
    cudaGetSymbolAddress(&p, g_v2);  float* v2 = (float*)p;
    cudaGetSymbolAddress(&p, g_m2);  float* m2 = (float*)p;

    cudaFuncSetAttribute(tc_gemm<D, S, 0, 1, true>,  cudaFuncAttributeMaxDynamicSharedMemorySize, SMEMB);
    cudaFuncSetAttribute(tc_gemm<S, D, 1, 1, false>, cudaFuncAttributeMaxDynamicSharedMemorySize, SMEMB);
    cudaFuncSetAttribute(tc_gemm<S, D, 1, 1, true>,  cudaFuncAttributeMaxDynamicSharedMemorySize, SMEMB);
    cudaFuncSetAttribute(tc_gemm<D, S, 2, 1, true>,  cudaFuncAttributeMaxDynamicSharedMemorySize, SMEMB);
    cudaFuncSetAttribute(tc_gemm<D, S, 2, 3, false>, cudaFuncAttributeMaxDynamicSharedMemorySize, SMEMB);

    const int nrows = NB * S;
    const size_t nA = (size_t)NB * S * S;
    const size_t nV = (size_t)NB * S * D;

    convert_hi_kernel<<<(unsigned)((nA / 4 + 255) / 256), 256>>>(A, Ah, nA);
    convert_hi_kernel<<<(unsigned)((nV / 4 + 255) / 256), 256>>>(V, Vh, nV);
    transpose_hilo_kernel<<<dim3(D / 32, S / 32, NB), dim3(32, 8)>>>(V, Vth, Vtl);
    rownorm_kernel<<<(nrows * 32 + 255) / 256, 256>>>(V, v2, D, nrows);

    // M0 = A @ V (1-product; feeds only distances)
    tc_gemm<D, S, 0, 1, true><<<dim3(D / 128, S / 128, NB), 256, SMEMB>>>(
        Ah, nullptr, Vth, nullptr, M, Mh, nullptr, nullptr);

    for (int it = 0; it < 3; ++it) {
        const bool last = (it == 2);
        rownorm_kernel<<<(nrows * 32 + 255) / 256, 256>>>(M, m2, D, nrows);
        // W = A / (cdist(M,V)+eps); dot via Mh·Vh (1-product)
        if (last)
            tc_gemm<S, D, 1, 1, true><<<dim3(S / 128, S / 128, NB), 256, SMEMB>>>(
                Mh, nullptr, Vh, nullptr, nullptr, Wh, Wl, A);
        else
            tc_gemm<S, D, 1, 1, false><<<dim3(S / 128, S / 128, NB), 256, SMEMB>>>(
                Mh, nullptr, Vh, nullptr, nullptr, Wh, nullptr, A);
        reduce_rinv_kernel<<<(NB * S + 255) / 256, 256>>>();
        // M = diag(1/l1) * (W @ V)
        if (last)
            tc_gemm<D, S, 2, 3, false><<<dim3(D / 128, S / 128, NB), 256, SMEMB>>>(
                Wh, Wl, Vth, Vtl, out, nullptr, nullptr, nullptr);
        else
            tc_gemm<D, S, 2, 1, true><<<dim3(D / 128, S / 128, NB), 256, SMEMB>>>(
                Wh, nullptr, Vth, nullptr, M, Mh, nullptr, nullptr);
    }
}

// round 7
// speedup vs baseline: 3.4105x; 1.2339x over previous
#include <cuda_runtime.h>
#include <cuda_bf16.h>
#include <cstdint>
#include <cstddef>

#define S 2048
#define D 512
#define NB 4
#define EPSI 0.01f
#define STAGES 3
#define SWZ(x) ((x) ^ (((x) >> 3) & 0x70))
#define SMEMB (98304 + 2048)

// ---------------- device scratch ----------------
__device__ __align__(128) __nv_bfloat16  g_Ah [(size_t)NB * S * S];
__device__ __align__(128) __nv_bfloat16  g_Wh [(size_t)NB * S * S];
__device__ __align__(128) __nv_bfloat16  g_Wl [(size_t)NB * S * S];
__device__ __align__(128) __nv_bfloat16  g_Mh [(size_t)NB * S * D];
__device__ __align__(128) __nv_bfloat16  g_Vh [(size_t)NB * S * D];
__device__ __align__(128) __nv_bfloat16  g_Vth[(size_t)NB * D * S];
__device__ __align__(128) __nv_bfloat16  g_Vtl[(size_t)NB * D * S];
__device__ __align__(128) float          g_rp [(size_t)NB * 16 * S];
__device__ __align__(128) float          g_mp [(size_t)NB * 4 * S];
__device__ float g_ri[NB * S];
__device__ float g_m2[NB * S];
__device__ float g_v2[NB * S];

// ---------------- PTX helpers (compute_103-safe only) ----------------
__device__ __forceinline__ uint32_t smem_u32(const void* p) {
    uint32_t a;
    asm("{ .reg .u64 t; cvta.to.shared.u64 t, %1; cvt.u32.u64 %0, t; }" : "=r"(a) : "l"(p));
    return a;
}
__device__ __forceinline__ void cpasync16(uint32_t smem, const void* g) {
    asm volatile("cp.async.cg.shared.global [%0], [%1], 16;" :: "r"(smem), "l"(g));
}
__device__ __forceinline__ void cp_commit() {
    asm volatile("cp.async.commit_group;" ::: "memory");
}
template <int N>
__device__ __forceinline__ void cp_wait() {
    asm volatile("cp.async.wait_group %0;" :: "n"(N) : "memory");
}
__device__ __forceinline__ void ldsm4(uint32_t* r, uint32_t addr) {
    asm volatile("ldmatrix.sync.aligned.m8n8.x4.shared.b16 {%0,%1,%2,%3}, [%4];"
                 : "=r"(r[0]), "=r"(r[1]), "=r"(r[2]), "=r"(r[3]) : "r"(addr));
}
__device__ __forceinline__ void mma_bf16(float* c, const uint32_t* a, uint32_t b0, uint32_t b1) {
    asm volatile("mma.sync.aligned.m16n8k16.row.col.f32.bf16.bf16.f32 "
                 "{%0,%1,%2,%3}, {%4,%5,%6,%7}, {%8,%9}, {%0,%1,%2,%3};"
                 : "+f"(c[0]), "+f"(c[1]), "+f"(c[2]), "+f"(c[3])
                 : "r"(a[0]), "r"(a[1]), "r"(a[2]), "r"(a[3]), "r"(b0), "r"(b1));
}
__device__ __forceinline__ unsigned pkb(__nv_bfloat16 a, __nv_bfloat16 b) {
    unsigned short ua = *(unsigned short*)&a, ub = *(unsigned short*)&b;
    return (unsigned)ua | ((unsigned)ub << 16);
}

// ---------------- small kernels ----------------
__global__ void rownorm_kernel(const float* __restrict__ X, float* __restrict__ out,
                               int cols, int nrows) {
    int warp = (blockIdx.x * blockDim.x + threadIdx.x) >> 5;
    int lane = threadIdx.x & 31;
    if (warp >= nrows) return;
    const float* row = X + (size_t)warp * cols;
    float s = 0.f;
    for (int c = lane * 4; c < cols; c += 128) {
        float4 v = *(const float4*)(row + c);
        s += v.x * v.x + v.y * v.y + v.z * v.z + v.w * v.w;
    }
    #pragma unroll
    for (int off = 16; off >= 1; off >>= 1) s += __shfl_xor_sync(0xffffffffu, s, off);
    if (lane == 0) out[warp] = s;
}

__global__ void convert_hi_kernel(const float* __restrict__ X,
                                  __nv_bfloat16* __restrict__ H, size_t n) {
    size_t i = ((size_t)blockIdx.x * blockDim.x + threadIdx.x) * 4;
    if (i >= n) return;
    float4 v = *(const float4*)(X + i);
    *(uint2*)(H + i) = make_uint2(pkb(__float2bfloat16(v.x), __float2bfloat16(v.y)),
                                  pkb(__float2bfloat16(v.z), __float2bfloat16(v.w)));
}

__global__ void transpose_hilo_kernel(const float* __restrict__ V,
                                      __nv_bfloat16* __restrict__ Th,
                                      __nv_bfloat16* __restrict__ Tl) {
    __shared__ float tile[32][33];
    int b = blockIdx.z, d0 = blockIdx.x * 32, j0 = blockIdx.y * 32;
    int tx = threadIdx.x, ty = threadIdx.y;
    #pragma unroll
    for (int r = 0; r < 32; r += 8)
        tile[ty + r][tx] = V[((size_t)b * S + j0 + ty + r) * D + d0 + tx];
    __syncthreads();
    #pragma unroll
    for (int r = 0; r < 32; r += 8) {
        float x = tile[tx][ty + r];
        __nv_bfloat16 h = __float2bfloat16(x);
        size_t o = ((size_t)b * D + d0 + ty + r) * S + j0 + tx;
        Th[o] = h;
        Tl[o] = __float2bfloat16(x - __bfloat162float(h));
    }
}

__global__ void reduce_rinv_kernel() {
    int idx = blockIdx.x * blockDim.x + threadIdx.x;
    if (idx >= NB * S) return;
    int b = idx / S, i = idx - b * S;
    float s = 0.f;
    #pragma unroll
    for (int t = 0; t < 16; ++t) s += g_rp[((size_t)(b * 16 + t)) * S + i];
    g_ri[idx] = 1.0f / fmaxf(s, 1e-12f);
}

__global__ void reduce_m2_kernel() {
    int idx = blockIdx.x * blockDim.x + threadIdx.x;
    if (idx >= NB * S) return;
    int b = idx / S, i = idx - b * S;
    float s = 0.f;
    #pragma unroll
    for (int t = 0; t < 4; ++t) s += g_mp[((size_t)(b * 4 + t)) * S + i];
    g_m2[idx] = s;
}

// ---------------- HMMA GEMM: C[128,128] = sum_k A[128,k]*B[128,k]^T ----------------
// NPROD=3: BK=32, rows [hi 32 bf16 | lo 32 bf16]; products ah*bh+ah*bl+al*bh.
// NPROD=1: BK=64, rows 64 bf16 hi-only; product ah*bh.
// smem: 3 stages x (A 16KB | B 16KB) = 96KB; red at +96KB.
// EPI 0: Mh + m2 partials (sc=1)     [GEMM0]
// EPI 1: weight epilogue -> Wh (+Wl if WLO) + L1 row partials   [GEMM1]
// EPI 2: Mh + m2 partials, sc=ri     [GEMM2 mid]
// EPI 3: fp32 out, sc=ri             [GEMM2 final, NPROD=3]
template <int NDIM, int KDIM, int EPI, int NPROD, bool WLO>
__global__ void __launch_bounds__(256, (NPROD == 1) ? 2 : 1)
tc_gemm(const __nv_bfloat16* __restrict__ Ah, const __nv_bfloat16* __restrict__ Al,
        const __nv_bfloat16* __restrict__ Bh, const __nv_bfloat16* __restrict__ Bl,
        float* __restrict__ dstF, __nv_bfloat16* __restrict__ dstH,
        __nv_bfloat16* __restrict__ dstL, const float* __restrict__ Ain) {
    constexpr int BKL = (NPROD == 1) ? 64 : 32;
    constexpr int SST = BKL / 16;
    extern __shared__ char dsm[];
    const uint32_t sb = smem_u32(dsm);
    float* red = (float*)(dsm + 98304);   // [128][4]

    const int b = blockIdx.z;
    const int mBase = blockIdx.y * 128;
    const int nBase = blockIdx.x * 128;
    const int tid = threadIdx.x;
    const int lane = tid & 31, wid = tid >> 5;
    const int wm = wid & 1, wn = wid >> 1;         // warp tile: M64 x N32

    const int grow_ld = tid >> 1;
    const int hsel = tid & 1;
    const __nv_bfloat16* pAh = Ah + (size_t)b * S * KDIM + (size_t)(mBase + grow_ld) * KDIM;
    const __nv_bfloat16* pAl = (NPROD == 3) ? Al + (size_t)b * S * KDIM + (size_t)(mBase + grow_ld) * KDIM : nullptr;
    const __nv_bfloat16* pBh = Bh + (size_t)b * NDIM * KDIM + (size_t)(nBase + grow_ld) * KDIM;
    const __nv_bfloat16* pBl = (NPROD == 3) ? Bl + (size_t)b * NDIM * KDIM + (size_t)(nBase + grow_ld) * KDIM : nullptr;

    const uint32_t rowb = (uint32_t)grow_ld * 128;
    const int nT = KDIM / BKL;

    auto load_chunk = [&](int t, int stage) {
        if (t < nT) {
            const int kb = t * BKL;
            const uint32_t ab = sb + stage * 16384;
            const uint32_t bb = sb + 49152 + stage * 16384;
            if (NPROD == 3) {
                #pragma unroll
                for (int j = 0; j < 2; ++j) {
                    const int seg = hsel * 2 + j;
                    cpasync16(ab + SWZ(rowb + seg * 16),      pAh + kb + seg * 8);
                    cpasync16(ab + SWZ(rowb + 64 + seg * 16), pAl + kb + seg * 8);
                    cpasync16(bb + SWZ(rowb + seg * 16),      pBh + kb + seg * 8);
                    cpasync16(bb + SWZ(rowb + 64 + seg * 16), pBl + kb + seg * 8);
                }
            } else {
                #pragma unroll
                for (int j = 0; j < 4; ++j) {
                    const int seg = hsel * 4 + j;
                    cpasync16(ab + SWZ(rowb + seg * 16), pAh + kb + seg * 8);
                    cpasync16(bb + SWZ(rowb + seg * 16), pBh + kb + seg * 8);
                }
            }
        }
        cp_commit();
    };

    float acc[4][4][4];
    #pragma unroll
    for (int i = 0; i < 4; ++i)
        #pragma unroll
        for (int j = 0; j < 4; ++j)
            #pragma unroll
            for (int e = 0; e < 4; ++e) acc[i][j][e] = 0.f;

    load_chunk(0, 0);
    load_chunk(1, 1);

    const int lrow = lane & 15, cseg = lane >> 4;

    int buf = 0, sld = 2;
    for (int t = 0; t < nT; ++t) {
        cp_wait<1>();
        __syncthreads();
        load_chunk(t + 2, sld);

        const uint32_t ab = sb + buf * 16384;
        const uint32_t bb = sb + 49152 + buf * 16384;

        #pragma unroll
        for (int s = 0; s < SST; ++s) {
            const uint32_t kcol = (uint32_t)(s * 2 + cseg) * 16;
            uint32_t bfh[2][4], bfl[2][4];
            #pragma unroll
            for (int g = 0; g < 2; ++g) {
                const uint32_t br = (uint32_t)(wn * 32 + g * 16 + lrow) * 128;
                ldsm4(bfh[g], bb + SWZ(br + kcol));
                if (NPROD == 3) ldsm4(bfl[g], bb + SWZ(br + 64 + kcol));
            }
            uint32_t afh[4][4], afl[4][4];
            #pragma unroll
            for (int mf = 0; mf < 4; ++mf) {
                const uint32_t arr = (uint32_t)(wm * 64 + mf * 16 + lrow) * 128;
                ldsm4(afh[mf], ab + SWZ(arr + kcol));
                if (NPROD == 3) ldsm4(afl[mf], ab + SWZ(arr + 64 + kcol));
            }
            #pragma unroll
            for (int mf = 0; mf < 4; ++mf)
                #pragma unroll
                for (int nf = 0; nf < 4; ++nf) {
                    const int g = nf >> 1, h = nf & 1;
                    mma_bf16(acc[mf][nf], afh[mf], bfh[g][h], bfh[g][h + 2]);
                    if (NPROD == 3) {
                        mma_bf16(acc[mf][nf], afh[mf], bfl[g][h], bfl[g][h + 2]);
                        mma_bf16(acc[mf][nf], afl[mf], bfh[g][h], bfh[g][h + 2]);
                    }
                }
        }
        buf = (buf == 2) ? 0 : buf + 1;
        sld = (sld == 2) ? 0 : sld + 1;
    }

    // ---------------- epilogue ----------------
    const int q = lane >> 2, tq = lane & 3;

    if (EPI == 1) {
        float v2c[4][2];
        #pragma unroll
        for (int nf = 0; nf < 4; ++nf) {
            float2 v2v = *(const float2*)(g_v2 + b * S + nBase + wn * 32 + nf * 8 + tq * 2);
            v2c[nf][0] = v2v.x; v2c[nf][1] = v2v.y;
        }
        #pragma unroll
        for (int mf = 0; mf < 4; ++mf) {
            #pragma unroll
            for (int r2 = 0; r2 < 2; ++r2) {
                const int lr = wm * 64 + mf * 16 + q + r2 * 8;
                const int gr = mBase + lr;
                const float m2v = g_m2[b * S + gr];
                const float* arow = Ain + ((size_t)b * S + gr) * S + nBase + wn * 32;
                __nv_bfloat16* whp = dstH + ((size_t)b * S + gr) * S + nBase + wn * 32;
                __nv_bfloat16* wlp = WLO ? dstL + ((size_t)b * S + gr) * S + nBase + wn * 32 : nullptr;
                float rs = 0.f;
                #pragma unroll
                for (int nf = 0; nf < 4; ++nf) {
                    float2 a2 = *(const float2*)(arow + nf * 8 + tq * 2);
                    float w0, w1;
                    {
                        float d2 = fmaxf(m2v + v2c[nf][0] - 2.f * acc[mf][nf][r2 * 2], 0.f);
                        w0 = __fdividef(a2.x, sqrtf(d2) + EPSI);
                        d2 = fmaxf(m2v + v2c[nf][1] - 2.f * acc[mf][nf][r2 * 2 + 1], 0.f);
                        w1 = __fdividef(a2.y, sqrtf(d2) + EPSI);
                    }
                    rs += fabsf(w0) + fabsf(w1);
                    __nv_bfloat16 h0 = __float2bfloat16(w0), h1 = __float2bfloat16(w1);
                    *(unsigned*)(whp + nf * 8 + tq * 2) = pkb(h0, h1);
                    if (WLO)
                        *(unsigned*)(wlp + nf * 8 + tq * 2) =
                            pkb(__float2bfloat16(w0 - __bfloat162float(h0)),
                                __float2bfloat16(w1 - __bfloat162float(h1)));
                }
                rs += __shfl_xor_sync(0xffffffffu, rs, 1);
                rs += __shfl_xor_sync(0xffffffffu, rs, 2);
                if (tq == 0) red[lr * 4 + wn] = rs;
            }
        }
        __syncthreads();
        if (tid < 128) {
            float s = red[tid * 4] + red[tid * 4 + 1] + red[tid * 4 + 2] + red[tid * 4 + 3];
            g_rp[((size_t)(b * 16 + blockIdx.x)) * S + mBase + tid] = s;
        }
    } else if (EPI == 3) {
        #pragma unroll
        for (int mf = 0; mf < 4; ++mf) {
            #pragma unroll
            for (int r2 = 0; r2 < 2; ++r2) {
                const int gr = mBase + wm * 64 + mf * 16 + q + r2 * 8;
                const float sc = g_ri[b * S + gr];
                float* fo = dstF + ((size_t)b * S + gr) * NDIM + nBase + wn * 32;
                #pragma unroll
                for (int nf = 0; nf < 4; ++nf) {
                    *(float2*)(fo + nf * 8 + tq * 2) =
                        make_float2(acc[mf][nf][r2 * 2] * sc, acc[mf][nf][r2 * 2 + 1] * sc);
                }
            }
        }
    } else {
        // EPI 0 / 2: bf16 Mh store + m2 partials
        #pragma unroll
        for (int mf = 0; mf < 4; ++mf) {
            #pragma unroll
            for (int r2 = 0; r2 < 2; ++r2) {
                const int lr = wm * 64 + mf * 16 + q + r2 * 8;
                const int gr = mBase + lr;
                const float sc = (EPI == 2) ? g_ri[b * S + gr] : 1.f;
                __nv_bfloat16* hp = dstH + ((size_t)b * S + gr) * NDIM + nBase + wn * 32;
                float rs = 0.f;
                #pragma unroll
                for (int nf = 0; nf < 4; ++nf) {
                    float o0 = acc[mf][nf][r2 * 2] * sc;
                    float o1 = acc[mf][nf][r2 * 2 + 1] * sc;
                    rs += o0 * o0 + o1 * o1;
                    *(unsigned*)(hp + nf * 8 + tq * 2) =
                        pkb(__float2bfloat16(o0), __float2bfloat16(o1));
                }
                rs += __shfl_xor_sync(0xffffffffu, rs, 1);
                rs += __shfl_xor_sync(0xffffffffu, rs, 2);
                if (tq == 0) red[lr * 4 + wn] = rs;
            }
        }
        __syncthreads();
        if (tid < 128) {
            float s = red[tid * 4] + red[tid * 4 + 1] + red[tid * 4 + 2] + red[tid * 4 + 3];
            g_mp[((size_t)(b * 4 + blockIdx.x)) * S + mBase + tid] = s;
        }
    }
}

// ---------------- launch ----------------
extern "C" void kernel_launch(void* const* d_in, const int* in_sizes, int n_in,
                              void* d_out, int out_size) {
    const float* A = (const float*)d_in[0];
    const float* V = (const float*)d_in[1];
    float* out = (float*)d_out;

    void* p;
    cudaGetSymbolAddress(&p, g_Ah);  __nv_bfloat16* Ah = (__nv_bfloat16*)p;
    cudaGetSymbolAddress(&p, g_Wh);  __nv_bfloat16* Wh = (__nv_bfloat16*)p;
    cudaGetSymbolAddress(&p, g_Wl);  __nv_bfloat16* Wl = (__nv_bfloat16*)p;
    cudaGetSymbolAddress(&p, g_Mh);  __nv_bfloat16* Mh = (__nv_bfloat16*)p;
    cudaGetSymbolAddress(&p, g_Vh);  __nv_bfloat16* Vh = (__nv_bfloat16*)p;
    cudaGetSymbolAddress(&p, g_Vth); __nv_bfloat16* Vth = (__nv_bfloat16*)p;
    cudaGetSymbolAddress(&p, g_Vtl); __nv_bfloat16* Vtl = (__nv_bfloat16*)p;
    cudaGetSymbolAddress(&p, g_v2);  float* v2 = (float*)p;

    cudaFuncSetAttribute(tc_gemm<D, S, 0, 1, false>, cudaFuncAttributeMaxDynamicSharedMemorySize, SMEMB);
    cudaFuncSetAttribute(tc_gemm<S, D, 1, 1, false>, cudaFuncAttributeMaxDynamicSharedMemorySize, SMEMB);
    cudaFuncSetAttribute(tc_gemm<S, D, 1, 1, true>,  cudaFuncAttributeMaxDynamicSharedMemorySize, SMEMB);
    cudaFuncSetAttribute(tc_gemm<D, S, 2, 1, false>, cudaFuncAttributeMaxDynamicSharedMemorySize, SMEMB);
    cudaFuncSetAttribute(tc_gemm<D, S, 3, 3, false>, cudaFuncAttributeMaxDynamicSharedMemorySize, SMEMB);

    const int nrows = NB * S;
    const size_t nA = (size_t)NB * S * S;
    const size_t nV = (size_t)NB * S * D;

    convert_hi_kernel<<<(unsigned)((nA / 4 + 255) / 256), 256>>>(A, Ah, nA);
    convert_hi_kernel<<<(unsigned)((nV / 4 + 255) / 256), 256>>>(V, Vh, nV);
    transpose_hilo_kernel<<<dim3(D / 32, S / 32, NB), dim3(32, 8)>>>(V, Vth, Vtl);
    rownorm_kernel<<<(nrows * 32 + 255) / 256, 256>>>(V, v2, D, nrows);

    // M0 = A @ V -> Mh + m2 partials
    tc_gemm<D, S, 0, 1, false><<<dim3(D / 128, S / 128, NB), 256, SMEMB>>>(
        Ah, nullptr, Vth, nullptr, nullptr, Mh, nullptr, nullptr);
    reduce_m2_kernel<<<(NB * S + 255) / 256, 256>>>();

    for (int it = 0; it < 3; ++it) {
        const bool last = (it == 2);
        // W = A / (cdist(M,V)+eps); dot via Mh·Vh
        if (last)
            tc_gemm<S, D, 1, 1, true><<<dim3(S / 128, S / 128, NB), 256, SMEMB>>>(
                Mh, nullptr, Vh, nullptr, nullptr, Wh, Wl, A);
        else
            tc_gemm<S, D, 1, 1, false><<<dim3(S / 128, S / 128, NB), 256, SMEMB>>>(
                Mh, nullptr, Vh, nullptr, nullptr, Wh, nullptr, A);
        reduce_rinv_kernel<<<(NB * S + 255) / 256, 256>>>();
        // M = diag(1/l1) * (W @ V)
        if (last) {
            tc_gemm<D, S, 3, 3, false><<<dim3(D / 128, S / 128, NB), 256, SMEMB>>>(
                Wh, Wl, Vth, Vtl, out, nullptr, nullptr, nullptr);
        } else {
            tc_gemm<D, S, 2, 1, false><<<dim3(D / 128, S / 128, NB), 256, SMEMB>>>(
                Wh, nullptr, Vth, nullptr, nullptr, Mh, nullptr, nullptr);
            reduce_m2_kernel<<<(NB * S + 255) / 256, 256>>>();
        }
    }
}